// round 12
// baseline (speedup 1.0000x reference)
#include <cuda_runtime.h>
#include <cuda_fp16.h>
#include <cstdint>
#include <math.h>

#define D       128
#define NMAX    8192
#define TAU_INV 10.0f
#define EX2K    14.4269504088896f   // TAU_INV * log2(e)
#define TM      128
#define NTT     64                  // tiles per dimension
#define NTILES_TRI (NTT * (NTT + 1) / 2)   // 2080
#define GMAIN   296                 // 2 CTAs per SM, persistent
#define GFIN    64                  // finalize blocks (128 rows each)

// scratch (device globals; no allocation allowed). g_cls/g_cnt/g_ticket are
// restored to zero by finalize's last block, so every graph replay sees them
// zeroed (statics start zeroed on first run).
__device__ __half g_ph[NMAX * D];      // normalized rows, f16 (B operand)
__device__ __half g_phA[NMAX * D];     // normalized rows * EX2K, f16 (A operand)
__device__ float  g_S[NMAX];           // exp-sum accumulators (zeroed by prep)
__device__ float  g_cls[2][D];         // per-class vector sums (from f16 table)
__device__ int    g_cnt[2];
__device__ unsigned int g_ticket;

// ---------------------------------------------------------------------------
__device__ __forceinline__ uint32_t smem_u32(const void* p) {
    uint32_t a;
    asm("{ .reg .u64 t; cvta.to.shared.u64 t, %1; cvt.u32.u64 %0, t; }"
        : "=r"(a) : "l"(p));
    return a;
}
__device__ __forceinline__ void ldsm4(uint32_t r[4], uint32_t addr) {
    asm volatile("ldmatrix.sync.aligned.m8n8.x4.shared.b16 {%0,%1,%2,%3}, [%4];"
                 : "=r"(r[0]), "=r"(r[1]), "=r"(r[2]), "=r"(r[3]) : "r"(addr));
}
// non-volatile — lets ptxas schedule MMAs between/around the LDSMs.
__device__ __forceinline__ void mma16816(float c[4], const uint32_t a[4],
                                         const uint32_t b[2]) {
    asm("mma.sync.aligned.m16n8k16.row.col.f32.f16.f16.f32 "
        "{%0,%1,%2,%3}, {%4,%5,%6,%7}, {%8,%9}, {%0,%1,%2,%3};"
        : "+f"(c[0]), "+f"(c[1]), "+f"(c[2]), "+f"(c[3])
        : "r"(a[0]), "r"(a[1]), "r"(a[2]), "r"(a[3]), "r"(b[0]), "r"(b[1]));
}
__device__ __forceinline__ void cp16(uint32_t saddr, const void* g) {
    asm volatile("cp.async.cg.shared.global [%0], [%1], 16;"
                 :: "r"(saddr), "l"(g) : "memory");
}
__device__ __forceinline__ float ex2(float x) {
    float r;
    asm("ex2.approx.f32 %0, %1;" : "=f"(r) : "f"(x));
    return r;
}
#define CP_COMMIT() asm volatile("cp.async.commit_group;" ::: "memory")
#define CP_WAIT(n)  asm volatile("cp.async.wait_group %0;" :: "n"(n) : "memory")

#define A_OFF  0u
#define B0_OFF 32768u
#define B1_OFF 65536u
#define SMEM_TOTAL 98304

// ---------------------------------------------------------------------------
// Kernel 1: pure streaming prep. Grid 1024 x 256, one row per warp.
// No atomics, no label reads. Writes both f16 tables, zeroes g_S.
// ---------------------------------------------------------------------------
__global__ __launch_bounds__(256)
void prep_kernel(const float* __restrict__ zi,
                 const float* __restrict__ zj,
                 int B, float* __restrict__ out) {
    int warp = threadIdx.x >> 5, lane = threadIdx.x & 31;
    int row  = blockIdx.x * 8 + warp;
    if (blockIdx.x == 0 && threadIdx.x == 0) out[0] = 0.f;

    const float* src = (row < B) ? (zi + (size_t)row * D)
                                 : (zj + (size_t)(row - B) * D);
    float4 v = ((const float4*)src)[lane];
    float ss = v.x * v.x + v.y * v.y + v.z * v.z + v.w * v.w;
    #pragma unroll
    for (int o = 16; o > 0; o >>= 1) ss += __shfl_xor_sync(0xffffffffu, ss, o);
    float s = 1.f / fmaxf(sqrtf(ss), 1e-8f);
    float4 pn = make_float4(v.x * s, v.y * s, v.z * s, v.w * s);

    __half2 h0 = __floats2half2_rn(pn.x, pn.y);
    __half2 h1 = __floats2half2_rn(pn.z, pn.w);
    uint2 u;
    u.x = *reinterpret_cast<unsigned int*>(&h0);
    u.y = *reinterpret_cast<unsigned int*>(&h1);
    ((uint2*)(g_ph + (size_t)row * D))[lane] = u;

    __half2 a0 = __floats2half2_rn(pn.x * EX2K, pn.y * EX2K);
    __half2 a1 = __floats2half2_rn(pn.z * EX2K, pn.w * EX2K);
    uint2 ua;
    ua.x = *reinterpret_cast<unsigned int*>(&a0);
    ua.y = *reinterpret_cast<unsigned int*>(&a1);
    ((uint2*)(g_phA + (size_t)row * D))[lane] = ua;

    if (lane == 0) g_S[row] = 0.f;
}

// ---------------------------------------------------------------------------
__device__ __forceinline__ void load_tile(uint32_t dst, const __half* table,
                                          int base, int tid) {
    for (int u = tid; u < TM * 16; u += 256) {
        int rr = u >> 4, cc = u & 15;
        cp16(dst + (uint32_t)rr * 256u + (uint32_t)((cc ^ (rr & 7)) << 4),
             table + (size_t)(base + rr) * D + cc * 8);
    }
}

// ---------------------------------------------------------------------------
// Kernel 2: persistent symmetric HMMA, software-pipelined K loop. (unchanged)
// ---------------------------------------------------------------------------
__global__ __launch_bounds__(256, 2)
void main_kernel() {
    extern __shared__ char sm[];
    const uint32_t smb = smem_u32(sm);

    const int tid = threadIdx.x, lane = tid & 31, wid = tid >> 5;
    const int warp_m = wid >> 2, warp_n = wid & 3;

    const int lo = (int)(((long long)blockIdx.x * NTILES_TRI) / GMAIN);
    const int hi = (int)(((long long)(blockIdx.x + 1) * NTILES_TRI) / GMAIN);

    int r = 0;
    while ((r + 1) * (2 * NTT - r) / 2 <= lo) r++;
    int c = r + (lo - r * (2 * NTT - r + 1) / 2);

    load_tile(smb + A_OFF, g_phA, r * TM, tid);
    load_tile(smb + B0_OFF, g_ph, c * TM, tid);
    CP_COMMIT();

    const int g = lane >> 3;
    uint32_t a_off[4], a_msk[4];
    #pragma unroll
    for (int mt = 0; mt < 4; mt++) {
        int row = warp_m * 64 + mt * 16 + (g & 1) * 8 + (lane & 7);
        a_off[mt] = smb + A_OFF + (uint32_t)row * 256u;
        a_msk[mt] = (uint32_t)(row & 7);
    }
    const int a_cadd = g >> 1;
    uint32_t b_row[2], b_msk[2];
    #pragma unroll
    for (int nt2 = 0; nt2 < 2; nt2++) {
        int row = warp_n * 32 + nt2 * 16 + (g >> 1) * 8 + (lane & 7);
        b_row[nt2] = (uint32_t)row * 256u;
        b_msk[nt2] = (uint32_t)(row & 7);
    }
    const int b_cadd = g & 1;

#define AADDR(mt, ks) (a_off[mt] + (uint32_t)(((2 * (ks) + a_cadd) ^ a_msk[mt]) << 4))
#define BADDR(n2, ks) (bbase + b_row[n2] + (uint32_t)(((2 * (ks) + b_cadd) ^ b_msk[n2]) << 4))

    float es[8];
    #pragma unroll
    for (int s = 0; s < 8; s++) es[s] = 0.f;
    int parity = 0;
    int accr = r;

    for (int t = lo; t < hi; t++) {
        const int tr = r, tc = c;
        const bool isdiag = (tr == tc);
        int nr = r, nc = c + 1;
        if (nc == NTT) { nr = r + 1; nc = nr; }
        const bool havenext = (t + 1 < hi);

        __syncthreads();
        if (havenext) {
            load_tile(smb + (parity ? B0_OFF : B1_OFF), g_ph, nc * TM, tid);
            CP_COMMIT();
            CP_WAIT(1);
        } else {
            CP_WAIT(0);
        }
        __syncthreads();

        const uint32_t bbase = smb + (parity ? B1_OFF : B0_OFF);
        float acc[4][4][4];
        #pragma unroll
        for (int mt = 0; mt < 4; mt++)
            #pragma unroll
            for (int nt = 0; nt < 4; nt++)
                #pragma unroll
                for (int k = 0; k < 4; k++) acc[mt][nt][k] = 0.f;

        uint32_t afb[2][4], bfb[2][2][4];
        ldsm4(bfb[0][0], BADDR(0, 0));
        ldsm4(bfb[0][1], BADDR(1, 0));
        ldsm4(afb[0], AADDR(0, 0));
        #pragma unroll
        for (int ks = 0; ks < 8; ks++) {
            const int kb = ks & 1;
            if (ks < 7) {
                ldsm4(bfb[kb ^ 1][0], BADDR(0, ks + 1));
                ldsm4(bfb[kb ^ 1][1], BADDR(1, ks + 1));
            }
            #pragma unroll
            for (int mt = 0; mt < 4; mt++) {
                const int ab = mt & 1;
                if (mt < 3)      ldsm4(afb[ab ^ 1], AADDR(mt + 1, ks));
                else if (ks < 7) ldsm4(afb[ab ^ 1], AADDR(0, ks + 1));
                #pragma unroll
                for (int nt = 0; nt < 4; nt++)
                    mma16816(acc[mt][nt], afb[ab], &bfb[kb][nt >> 1][(nt & 1) * 2]);
            }
        }

        float csl[8];
        #pragma unroll
        for (int s = 0; s < 8; s++) csl[s] = 0.f;
        #pragma unroll
        for (int nt = 0; nt < 4; nt++) {
            #pragma unroll
            for (int mt = 0; mt < 4; mt++) {
                #pragma unroll
                for (int q = 0; q < 4; q++) {
                    float e = ex2(acc[mt][nt][q]);
                    if (isdiag) {
                        int jl = warp_n * 32 + nt * 8 + (lane & 3) * 2 + (q & 1);
                        int il = warp_m * 64 + mt * 16 + (lane >> 2) + ((q < 2) ? 0 : 8);
                        if (jl == il) e = 0.f;
                    }
                    es[mt * 2 + (q >> 1)] += e;
                    csl[nt * 2 + (q & 1)] += e;
                }
            }
        }
        if (!isdiag) {
            int colBase = tc * TM;
            #pragma unroll
            for (int s = 0; s < 8; s++) {
                float v = csl[s];
                v += __shfl_xor_sync(0xffffffffu, v, 4);
                v += __shfl_xor_sync(0xffffffffu, v, 8);
                v += __shfl_xor_sync(0xffffffffu, v, 16);
                if (lane < 4)
                    atomicAdd(&g_S[colBase + warp_n * 32 + (s >> 1) * 8 + lane * 2 + (s & 1)], v);
            }
        }

        if (havenext && nr != tr) {
            int rowBase = accr * TM;
            #pragma unroll
            for (int s = 0; s < 8; s++) {
                float e = es[s];
                e += __shfl_xor_sync(0xffffffffu, e, 1);
                e += __shfl_xor_sync(0xffffffffu, e, 2);
                if ((lane & 3) == 0)
                    atomicAdd(&g_S[rowBase + warp_m * 64 + (s >> 1) * 16 +
                                   (lane >> 2) + (s & 1) * 8], e);
                es[s] = 0.f;
            }
            accr = nr;
            __syncthreads();
            load_tile(smb + A_OFF, g_phA, nr * TM, tid);
            CP_COMMIT();
        }
        r = nr; c = nc; parity ^= 1;
    }

    {
        int rowBase = accr * TM;
        #pragma unroll
        for (int s = 0; s < 8; s++) {
            float e = es[s];
            e += __shfl_xor_sync(0xffffffffu, e, 1);
            e += __shfl_xor_sync(0xffffffffu, e, 2);
            if ((lane & 3) == 0)
                atomicAdd(&g_S[rowBase + warp_m * 64 + (s >> 1) * 16 +
                               (lane >> 2) + (s & 1) * 8], e);
        }
    }
#undef AADDR
#undef BADDR
}

// ---------------------------------------------------------------------------
// Kernel 3: finalize. Grid GFIN x 256, 128 rows per block.
//  (a) sum log S_i
//  (b) class sums + count from the f16 table (16 rows per warp)
//  (c) ticket: last block adds -tau_inv*(||S_c||^2-cnt_c)/(cnt_c-1) and
//      resets g_cls/g_cnt/g_ticket for the next graph replay.
// ---------------------------------------------------------------------------
__global__ __launch_bounds__(256)
void finalize_kernel(const int* __restrict__ y, int B, float* __restrict__ out) {
    __shared__ float ws[8];
    __shared__ float cls_b[2][D];
    __shared__ int   cnt_b;
    __shared__ bool  is_last;
    int t = threadIdx.x, lane = t & 31, warp = t >> 5;
    if (t < 2 * D) ((float*)cls_b)[t] = 0.f;
    if (t == 0) cnt_b = 0;

    // (a) log part — 128 rows per block
    float local = 0.f;
    if (t < 128) local = logf(g_S[blockIdx.x * 128 + t]);
    #pragma unroll
    for (int o = 16; o > 0; o >>= 1) local += __shfl_xor_sync(0xffffffffu, local, o);
    if (lane == 0) ws[warp] = local;
    __syncthreads();
    if (t < 8) {
        float v = ws[t];
        #pragma unroll
        for (int o = 4; o > 0; o >>= 1) v += __shfl_xor_sync(0x000000ffu, v, o);
        if (t == 0) atomicAdd(out, v);
    }

    // (b) class sums from f16 table: warp handles 16 rows, lane = 4 dims
    float a0[4] = {0.f, 0.f, 0.f, 0.f}, a1[4] = {0.f, 0.f, 0.f, 0.f};
    int   c1 = 0;
    int rb = blockIdx.x * 128 + warp * 16;
    #pragma unroll 4
    for (int i = 0; i < 16; i++) {
        int row = rb + i;
        int lbl = (row < B) ? y[row] : y[row - B];
        uint2 u = ((const uint2*)(g_ph + (size_t)row * D))[lane];
        __half2 h0 = *reinterpret_cast<__half2*>(&u.x);
        __half2 h1 = *reinterpret_cast<__half2*>(&u.y);
        float2 f0 = __half22float2(h0), f1 = __half22float2(h1);
        if (lbl) {
            a1[0] += f0.x; a1[1] += f0.y; a1[2] += f1.x; a1[3] += f1.y; c1++;
        } else {
            a0[0] += f0.x; a0[1] += f0.y; a0[2] += f1.x; a0[3] += f1.y;
        }
    }
    #pragma unroll
    for (int k = 0; k < 4; k++) {
        atomicAdd(&cls_b[0][lane * 4 + k], a0[k]);
        atomicAdd(&cls_b[1][lane * 4 + k], a1[k]);
    }
    if (lane == 0) atomicAdd(&cnt_b, c1);
    __syncthreads();
    if (t < 2 * D) atomicAdd(&((float*)g_cls)[t], ((float*)cls_b)[t]);
    if (t == 0) atomicAdd(&g_cnt[1], cnt_b);

    // (c) last block: class-norm term + reset
    __threadfence();
    __syncthreads();
    if (t == 0) is_last = (atomicAdd(&g_ticket, 1u) == (unsigned)(GFIN - 1));
    __syncthreads();
    if (!is_last) return;
    __threadfence();

    if (warp < 2) {
        float4 cv = ((const float4*)(g_cls[warp]))[lane];
        float nsq = cv.x * cv.x + cv.y * cv.y + cv.z * cv.z + cv.w * cv.w;
        #pragma unroll
        for (int o = 16; o > 0; o >>= 1) nsq += __shfl_xor_sync(0xffffffffu, nsq, o);
        if (lane == 0) {
            float cnt = (warp == 1) ? (float)g_cnt[1] : (float)(NMAX - g_cnt[1]);
            atomicAdd(out, -TAU_INV * (nsq - cnt) / (cnt - 1.f));
        }
    }
    __syncthreads();
    if (t < 2 * D) ((float*)g_cls)[t] = 0.f;
    if (t < 2) g_cnt[t] = 0;
    if (t == 0) g_ticket = 0u;
}

// ---------------------------------------------------------------------------
extern "C" void kernel_launch(void* const* d_in, const int* in_sizes, int n_in,
                              void* d_out, int out_size) {
    const float* zi = (const float*)d_in[0];
    const float* zj = (const float*)d_in[1];
    const int*   y  = (const int*)d_in[2];
    int B = in_sizes[2];
    int N = 2 * B;

    prep_kernel<<<N / 8, 256>>>(zi, zj, B, (float*)d_out);

    cudaFuncSetAttribute(main_kernel, cudaFuncAttributeMaxDynamicSharedMemorySize,
                         SMEM_TOTAL);
    main_kernel<<<GMAIN, 256, SMEM_TOTAL>>>();

    finalize_kernel<<<GFIN, 256>>>(y, B, (float*)d_out);
}